// round 1
// baseline (speedup 1.0000x reference)
#include <cuda_runtime.h>
#include <math.h>
#include <stdint.h>

#define NMAX 100000
#define EMAX 1600000
#define ETMAX (EMAX + NMAX)

// ---------------- scratch (device globals; no allocation allowed) ----------------
__device__ float  g_h1[NMAX * 128];     // layer1 pre-activation features  (51.2 MB)
__device__ float  g_out1[NMAX * 128];   // layer1 aggregated output        (51.2 MB)
__device__ float4 g_as1[NMAX];          // alpha_src layer1 (4 heads)
__device__ float4 g_ad1[NMAX];          // alpha_dst layer1
__device__ int    g_m1[NMAX * 4];       // segment max (sortable-int), layer1
__device__ float  g_den1[NMAX * 4];     // segment sum of exp, layer1
__device__ float4 g_ex1[ETMAX];         // per-edge exp values, layer1    (27.2 MB)
__device__ float  g_h2[NMAX * 8];       // layer2 features
__device__ float  g_as2[NMAX];
__device__ float  g_ad2[NMAX];
__device__ int    g_m2[NMAX];
__device__ float  g_den2[NMAX];
__device__ float  g_out2[NMAX * 8];
__device__ float  g_ex2[ETMAX];

// ---------------- helpers ----------------
__device__ __forceinline__ float lrelu(float v) { return v > 0.f ? v : 0.2f * v; }
__device__ __forceinline__ float eluf(float v)  { return v > 0.f ? v : expm1f(v); }
// monotonic float<->int mapping so plain int atomicMax works for any sign
__device__ __forceinline__ int   f2o(float f) { int i = __float_as_int(f); return i >= 0 ? i : (i ^ 0x7fffffff); }
__device__ __forceinline__ float o2f(int i)   { return __int_as_float(i >= 0 ? i : (i ^ 0x7fffffff)); }

__device__ __forceinline__ void red_add_v4(float* p, float a, float b, float c, float d) {
    asm volatile("red.global.add.v4.f32 [%0], {%1, %2, %3, %4};"
                 :: "l"(p), "f"(a), "f"(b), "f"(c), "f"(d) : "memory");
}

// ---------------- init ----------------
__global__ void init_kernel(int N) {
    int i = blockIdx.x * blockDim.x + threadIdx.x;
    float4 z = make_float4(0.f, 0.f, 0.f, 0.f);
    if (i < N * 32) ((float4*)g_out1)[i] = z;
    if (i < N * 2)  ((float4*)g_out2)[i] = z;
    if (i < N) {
        const int NEG = (int)0x80808080;  // far below any sortable real value; self-loops guarantee overwrite
        ((int4*)g_m1)[i] = make_int4(NEG, NEG, NEG, NEG);
        ((float4*)g_den1)[i] = z;
        g_m2[i] = NEG;
        g_den2[i] = 0.f;
    }
}

// ---------------- layer1 GEMM: h1 = x @ W1  (128x128 tile, 8x8 microtile) ----------------
__global__ void gemm1_kernel(const float* __restrict__ x, const float* __restrict__ W, int N) {
    extern __shared__ float sm[];
    float* xs = sm;              // transposed x tile: xs[k*132 + r], k=0..127, r=0..127
    float* ws = sm + 128 * 132;  // W: ws[k*132 + j]
    int tid = threadIdx.x;
    int base = blockIdx.x * 128;

    for (int i = tid; i < 128 * 32; i += 256) {
        int k = i >> 5, c4 = i & 31;
        float4 v = ((const float4*)W)[i];
        *(float4*)(ws + k * 132 + c4 * 4) = v;
    }
    for (int i = tid; i < 128 * 32; i += 256) {
        int r = i >> 5, c4 = i & 31;
        int gr = base + r;
        float4 v = make_float4(0.f, 0.f, 0.f, 0.f);
        if (gr < N) v = ((const float4*)x)[gr * 32 + c4];
        xs[(c4 * 4 + 0) * 132 + r] = v.x;
        xs[(c4 * 4 + 1) * 132 + r] = v.y;
        xs[(c4 * 4 + 2) * 132 + r] = v.z;
        xs[(c4 * 4 + 3) * 132 + r] = v.w;
    }
    __syncthreads();

    int ty = tid >> 4, tx = tid & 15;
    int r0 = ty * 8, c0 = tx * 8;
    float acc[8][8];
#pragma unroll
    for (int i = 0; i < 8; i++)
#pragma unroll
        for (int j = 0; j < 8; j++) acc[i][j] = 0.f;

#pragma unroll 8
    for (int k = 0; k < 128; k++) {
        const float* xk = xs + k * 132;
        const float* wk = ws + k * 132;
        float a[8], b[8];
        *(float4*)(a)     = *(const float4*)(xk + r0);
        *(float4*)(a + 4) = *(const float4*)(xk + r0 + 4);
        *(float4*)(b)     = *(const float4*)(wk + c0);
        *(float4*)(b + 4) = *(const float4*)(wk + c0 + 4);
#pragma unroll
        for (int i = 0; i < 8; i++)
#pragma unroll
            for (int j = 0; j < 8; j++)
                acc[i][j] = fmaf(a[i], b[j], acc[i][j]);
    }

#pragma unroll
    for (int i = 0; i < 8; i++) {
        int gr = base + r0 + i;
        if (gr < N) {
            float4 v0 = make_float4(acc[i][0], acc[i][1], acc[i][2], acc[i][3]);
            float4 v1 = make_float4(acc[i][4], acc[i][5], acc[i][6], acc[i][7]);
            *(float4*)&g_h1[gr * 128 + c0]     = v0;
            *(float4*)&g_h1[gr * 128 + c0 + 4] = v1;
        }
    }
}

// ---------------- layer1 attention scores per node ----------------
__global__ void alpha1_kernel(const float* __restrict__ asrc, const float* __restrict__ adst, int N) {
    int n = blockIdx.x * blockDim.x + threadIdx.x;
    if (n >= N) return;
    float s[4], d[4];
#pragma unroll
    for (int h = 0; h < 4; h++) { s[h] = 0.f; d[h] = 0.f; }
    const float4* hp = (const float4*)&g_h1[n * 128];
#pragma unroll
    for (int h = 0; h < 4; h++) {
#pragma unroll
        for (int c4 = 0; c4 < 8; c4++) {
            float4 hv = hp[h * 8 + c4];
            float4 sv = ((const float4*)asrc)[h * 8 + c4];
            float4 dv = ((const float4*)adst)[h * 8 + c4];
            s[h] += hv.x * sv.x + hv.y * sv.y + hv.z * sv.z + hv.w * sv.w;
            d[h] += hv.x * dv.x + hv.y * dv.y + hv.z * dv.z + hv.w * dv.w;
        }
    }
    g_as1[n] = make_float4(s[0], s[1], s[2], s[3]);
    g_ad1[n] = make_float4(d[0], d[1], d[2], d[3]);
}

// ---------------- layer1 edge passes ----------------
__global__ void max1_kernel(const int* __restrict__ ei, int E, int Etot) {
    int idx = blockIdx.x * blockDim.x + threadIdx.x;
    if (idx >= Etot) return;
    int src, dst;
    if (idx < E) { src = ei[idx]; dst = ei[E + idx]; } else { src = dst = idx - E; }
    float4 s = g_as1[src], d = g_ad1[dst];
    atomicMax(&g_m1[dst * 4 + 0], f2o(lrelu(s.x + d.x)));
    atomicMax(&g_m1[dst * 4 + 1], f2o(lrelu(s.y + d.y)));
    atomicMax(&g_m1[dst * 4 + 2], f2o(lrelu(s.z + d.z)));
    atomicMax(&g_m1[dst * 4 + 3], f2o(lrelu(s.w + d.w)));
}

__global__ void denom1_kernel(const int* __restrict__ ei, int E, int Etot) {
    int idx = blockIdx.x * blockDim.x + threadIdx.x;
    if (idx >= Etot) return;
    int src, dst;
    if (idx < E) { src = ei[idx]; dst = ei[E + idx]; } else { src = dst = idx - E; }
    float4 s = g_as1[src], d = g_ad1[dst];
    int4 m = ((const int4*)g_m1)[dst];
    float e0 = expf(lrelu(s.x + d.x) - o2f(m.x));
    float e1 = expf(lrelu(s.y + d.y) - o2f(m.y));
    float e2 = expf(lrelu(s.z + d.z) - o2f(m.z));
    float e3 = expf(lrelu(s.w + d.w) - o2f(m.w));
    g_ex1[idx] = make_float4(e0, e1, e2, e3);
    atomicAdd(&g_den1[dst * 4 + 0], e0);
    atomicAdd(&g_den1[dst * 4 + 1], e1);
    atomicAdd(&g_den1[dst * 4 + 2], e2);
    atomicAdd(&g_den1[dst * 4 + 3], e3);
}

__global__ void scatter1_kernel(const int* __restrict__ ei, int E, int Etot) {
    int t = blockIdx.x * blockDim.x + threadIdx.x;
    if (t >= Etot * 4) return;
    int edge = t >> 2, head = t & 3;
    int src, dst;
    if (edge < E) { src = ei[edge]; dst = ei[E + edge]; } else { src = dst = edge - E; }
    float ex  = ((const float*)g_ex1)[t];
    float den = g_den1[dst * 4 + head];
    float alpha = ex / (den + 1e-16f);
    const float4* hp = (const float4*)&g_h1[src * 128 + head * 32];
    float* op = &g_out1[dst * 128 + head * 32];
#pragma unroll
    for (int i = 0; i < 8; i++) {
        float4 v = hp[i];
        red_add_v4(op + i * 4, v.x * alpha, v.y * alpha, v.z * alpha, v.w * alpha);
    }
}

// ---------------- layer2: elu(out1+b1) @ W2, plus attention scores ----------------
__global__ void layer2_kernel(const float* __restrict__ W2, const float* __restrict__ b1,
                              const float* __restrict__ asrc2, const float* __restrict__ adst2, int N) {
    __shared__ float w2s[128 * 8];
    __shared__ float b1s[128];
    __shared__ float s2s[8], d2s[8];
    int tid = threadIdx.x;
    for (int i = tid; i < 1024; i += 256) w2s[i] = W2[i];
    if (tid < 128) b1s[tid] = b1[tid];
    if (tid < 8) { s2s[tid] = asrc2[tid]; d2s[tid] = adst2[tid]; }
    __syncthreads();
    int n = blockIdx.x * 256 + tid;
    if (n >= N) return;
    float acc[8];
#pragma unroll
    for (int c = 0; c < 8; c++) acc[c] = 0.f;
    const float4* op = (const float4*)&g_out1[n * 128];
#pragma unroll 8
    for (int k4 = 0; k4 < 32; k4++) {
        float4 v = op[k4];
        float vv[4] = {v.x, v.y, v.z, v.w};
#pragma unroll
        for (int j = 0; j < 4; j++) {
            int k = k4 * 4 + j;
            float tv = eluf(vv[j] + b1s[k]);
#pragma unroll
            for (int c = 0; c < 8; c++) acc[c] = fmaf(tv, w2s[k * 8 + c], acc[c]);
        }
    }
    ((float4*)&g_h2[n * 8])[0] = make_float4(acc[0], acc[1], acc[2], acc[3]);
    ((float4*)&g_h2[n * 8])[1] = make_float4(acc[4], acc[5], acc[6], acc[7]);
    float s = 0.f, d = 0.f;
#pragma unroll
    for (int c = 0; c < 8; c++) { s += acc[c] * s2s[c]; d += acc[c] * d2s[c]; }
    g_as2[n] = s;
    g_ad2[n] = d;
}

// ---------------- layer2 edge passes (1 head) ----------------
__global__ void max2_kernel(const int* __restrict__ ei, int E, int Etot) {
    int idx = blockIdx.x * blockDim.x + threadIdx.x;
    if (idx >= Etot) return;
    int src, dst;
    if (idx < E) { src = ei[idx]; dst = ei[E + idx]; } else { src = dst = idx - E; }
    atomicMax(&g_m2[dst], f2o(lrelu(g_as2[src] + g_ad2[dst])));
}

__global__ void denom2_kernel(const int* __restrict__ ei, int E, int Etot) {
    int idx = blockIdx.x * blockDim.x + threadIdx.x;
    if (idx >= Etot) return;
    int src, dst;
    if (idx < E) { src = ei[idx]; dst = ei[E + idx]; } else { src = dst = idx - E; }
    float e = lrelu(g_as2[src] + g_ad2[dst]);
    float ex = expf(e - o2f(g_m2[dst]));
    g_ex2[idx] = ex;
    atomicAdd(&g_den2[dst], ex);
}

__global__ void scatter2_kernel(const int* __restrict__ ei, int E, int Etot) {
    int idx = blockIdx.x * blockDim.x + threadIdx.x;
    if (idx >= Etot) return;
    int src, dst;
    if (idx < E) { src = ei[idx]; dst = ei[E + idx]; } else { src = dst = idx - E; }
    float alpha = g_ex2[idx] / (g_den2[dst] + 1e-16f);
    const float4* hp = (const float4*)&g_h2[src * 8];
    float* op = &g_out2[dst * 8];
    float4 v0 = hp[0], v1 = hp[1];
    red_add_v4(op,     v0.x * alpha, v0.y * alpha, v0.z * alpha, v0.w * alpha);
    red_add_v4(op + 4, v1.x * alpha, v1.y * alpha, v1.z * alpha, v1.w * alpha);
}

// ---------------- final: sigmoid(elu(out2+b2) @ Wlin + blin) ----------------
__global__ void final_kernel(const float* __restrict__ b2, const float* __restrict__ Wlin,
                             const float* __restrict__ blin, float* __restrict__ out, int N) {
    int n = blockIdx.x * blockDim.x + threadIdx.x;
    if (n >= N) return;
    const float4* op = (const float4*)&g_out2[n * 8];
    float4 v0 = op[0], v1 = op[1];
    float o[8] = {v0.x, v0.y, v0.z, v0.w, v1.x, v1.y, v1.z, v1.w};
    float y = blin[0];
#pragma unroll
    for (int j = 0; j < 8; j++) {
        float t = eluf(o[j] + b2[j]);
        y = fmaf(t, Wlin[j], y);
    }
    out[n] = 1.f / (1.f + expf(-y));
}

// ---------------- launch ----------------
extern "C" void kernel_launch(void* const* d_in, const int* in_sizes, int n_in,
                              void* d_out, int out_size) {
    const float* x    = (const float*)d_in[0];
    const int*   ei   = (const int*)d_in[1];
    // d_in[2] edge_attr: unused (edge_dim=None)
    const float* W1   = (const float*)d_in[3];
    const float* as1  = (const float*)d_in[4];
    const float* ad1  = (const float*)d_in[5];
    const float* b1   = (const float*)d_in[6];
    const float* W2   = (const float*)d_in[7];
    const float* as2w = (const float*)d_in[8];
    const float* ad2w = (const float*)d_in[9];
    const float* b2   = (const float*)d_in[10];
    const float* Wlin = (const float*)d_in[11];
    const float* blin = (const float*)d_in[12];
    float* out = (float*)d_out;

    int N = in_sizes[0] / 128;
    int E = in_sizes[1] / 2;
    int Etot = E + N;
    const int TB = 256;
    const int SMEM_GEMM = 2 * 128 * 132 * 4;  // 135168 bytes

    cudaFuncSetAttribute(gemm1_kernel, cudaFuncAttributeMaxDynamicSharedMemorySize, SMEM_GEMM);

    init_kernel<<<(N * 32 + TB - 1) / TB, TB>>>(N);
    gemm1_kernel<<<(N + 127) / 128, 256, SMEM_GEMM>>>(x, W1, N);
    alpha1_kernel<<<(N + TB - 1) / TB, TB>>>(as1, ad1, N);
    max1_kernel<<<(Etot + TB - 1) / TB, TB>>>(ei, E, Etot);
    denom1_kernel<<<(Etot + TB - 1) / TB, TB>>>(ei, E, Etot);
    scatter1_kernel<<<(Etot * 4 + TB - 1) / TB, TB>>>(ei, E, Etot);
    layer2_kernel<<<(N + TB - 1) / TB, TB>>>(W2, b1, as2w, ad2w, N);
    max2_kernel<<<(Etot + TB - 1) / TB, TB>>>(ei, E, Etot);
    denom2_kernel<<<(Etot + TB - 1) / TB, TB>>>(ei, E, Etot);
    scatter2_kernel<<<(Etot + TB - 1) / TB, TB>>>(ei, E, Etot);
    final_kernel<<<(N + TB - 1) / TB, TB>>>(b2, Wlin, blin, out, N);
}

// round 2
// speedup vs baseline: 2.0607x; 2.0607x over previous
#include <cuda_runtime.h>
#include <math.h>
#include <stdint.h>

#define NMAX 100000
#define EMAX 1600000
#define ETMAX (EMAX + NMAX)
#define SCAN_CHUNK 512

// ---------------- scratch (device globals; no allocation allowed) ----------------
__device__ float  g_h1[NMAX * 128];      // layer1 features (51.2 MB)
__device__ float  g_out1[NMAX * 128];    // layer1 aggregated (51.2 MB)
__device__ float4 g_as1[NMAX];           // alpha_src layer1 (4 heads)
__device__ float4 g_ad1[NMAX];           // alpha_dst layer1
__device__ float  g_h2[NMAX * 8];
__device__ float  g_as2[NMAX];
__device__ float  g_ad2[NMAX];
__device__ float  g_out2[NMAX * 8];
// CSR scratch
__device__ int    g_deg[NMAX];
__device__ int    g_rowstart[NMAX + 1];
__device__ int    g_fill[NMAX];
__device__ int    g_srcs[ETMAX];         // src ids grouped by dst (6.8 MB)
__device__ int    g_csum[(NMAX + SCAN_CHUNK - 1) / SCAN_CHUNK];
__device__ int    g_coff[(NMAX + SCAN_CHUNK - 1) / SCAN_CHUNK];

// ---------------- helpers ----------------
__device__ __forceinline__ float lrelu(float v) { return v > 0.f ? v : 0.2f * v; }
__device__ __forceinline__ float eluf(float v)  { return v > 0.f ? v : (__expf(v) - 1.f); }
__device__ __forceinline__ float wmaxf(float v) {
#pragma unroll
    for (int o = 16; o; o >>= 1) v = fmaxf(v, __shfl_xor_sync(0xffffffffu, v, o));
    return v;
}
__device__ __forceinline__ float wsumf(float v) {
#pragma unroll
    for (int o = 16; o; o >>= 1) v += __shfl_xor_sync(0xffffffffu, v, o);
    return v;
}

// ---------------- CSR build ----------------
__global__ void zero_deg_kernel(int N) {
    int i = blockIdx.x * blockDim.x + threadIdx.x;
    if (i < N) g_deg[i] = 0;
}

__global__ void count_kernel(const int* __restrict__ ei, int E, int Etot) {
    int idx = blockIdx.x * blockDim.x + threadIdx.x;
    if (idx >= Etot) return;
    int dst = (idx < E) ? ei[E + idx] : (idx - E);
    atomicAdd(&g_deg[dst], 1);
}

__global__ void scan1_kernel(int N) {  // per-chunk sums
    __shared__ int sh[SCAN_CHUNK];
    int t = threadIdx.x;
    int i = blockIdx.x * SCAN_CHUNK + t;
    sh[t] = (i < N) ? g_deg[i] : 0;
    __syncthreads();
#pragma unroll
    for (int s = SCAN_CHUNK / 2; s > 0; s >>= 1) {
        if (t < s) sh[t] += sh[t + s];
        __syncthreads();
    }
    if (t == 0) g_csum[blockIdx.x] = sh[0];
}

__global__ void scan2_kernel(int nch) {  // single-block exclusive scan of chunk sums
    __shared__ int sh[SCAN_CHUNK];
    int t = threadIdx.x;
    int v = (t < nch) ? g_csum[t] : 0;
    sh[t] = v;
    __syncthreads();
#pragma unroll
    for (int off = 1; off < SCAN_CHUNK; off <<= 1) {
        int add = (t >= off) ? sh[t - off] : 0;
        __syncthreads();
        sh[t] += add;
        __syncthreads();
    }
    if (t < nch) g_coff[t] = sh[t] - v;  // exclusive
}

__global__ void scan3_kernel(int N, int Etot) {  // chunk-local exclusive scan + offset
    __shared__ int sh[SCAN_CHUNK];
    int t = threadIdx.x;
    int i = blockIdx.x * SCAN_CHUNK + t;
    int v = (i < N) ? g_deg[i] : 0;
    sh[t] = v;
    __syncthreads();
#pragma unroll
    for (int off = 1; off < SCAN_CHUNK; off <<= 1) {
        int add = (t >= off) ? sh[t - off] : 0;
        __syncthreads();
        sh[t] += add;
        __syncthreads();
    }
    if (i < N) {
        int excl = sh[t] - v + g_coff[blockIdx.x];
        g_rowstart[i] = excl;
        g_fill[i] = excl;
    }
    if (blockIdx.x == 0 && t == 0) g_rowstart[N] = Etot;
}

__global__ void fill_kernel(const int* __restrict__ ei, int E, int Etot) {
    int idx = blockIdx.x * blockDim.x + threadIdx.x;
    if (idx >= Etot) return;
    int src, dst;
    if (idx < E) { src = ei[idx]; dst = ei[E + idx]; } else { src = dst = idx - E; }
    int p = atomicAdd(&g_fill[dst], 1);
    g_srcs[p] = src;
}

// ---------------- layer1 GEMM + alpha fused: h1 = x@W1, as1/ad1 = h1 . a ----------------
__global__ void gemm1_kernel(const float* __restrict__ x, const float* __restrict__ W,
                             const float* __restrict__ asrc, const float* __restrict__ adst, int N) {
    extern __shared__ float sm[];
    float* xs = sm;              // x^T tile: xs[k*132 + r]
    float* ws = sm + 128 * 132;  // W tile:   ws[k*132 + j]
    float* rs = sm;              // reuse: s partials [128][16]
    float* rd = sm + 128 * 16;   // d partials [128][16]
    int tid = threadIdx.x;
    int base = blockIdx.x * 128;

    for (int i = tid; i < 128 * 32; i += 256) {
        int k = i >> 5, c4 = i & 31;
        float4 v = ((const float4*)W)[i];
        *(float4*)(ws + k * 132 + c4 * 4) = v;
    }
    for (int i = tid; i < 128 * 32; i += 256) {
        int r = i >> 5, c4 = i & 31;
        int gr = base + r;
        float4 v = make_float4(0.f, 0.f, 0.f, 0.f);
        if (gr < N) v = ((const float4*)x)[gr * 32 + c4];
        xs[(c4 * 4 + 0) * 132 + r] = v.x;
        xs[(c4 * 4 + 1) * 132 + r] = v.y;
        xs[(c4 * 4 + 2) * 132 + r] = v.z;
        xs[(c4 * 4 + 3) * 132 + r] = v.w;
    }
    __syncthreads();

    int ty = tid >> 4, tx = tid & 15;
    int r0 = ty * 8, c0 = tx * 8;
    float acc[8][8];
#pragma unroll
    for (int i = 0; i < 8; i++)
#pragma unroll
        for (int j = 0; j < 8; j++) acc[i][j] = 0.f;

#pragma unroll 8
    for (int k = 0; k < 128; k++) {
        const float* xk = xs + k * 132;
        const float* wk = ws + k * 132;
        float a[8], b[8];
        *(float4*)(a)     = *(const float4*)(xk + r0);
        *(float4*)(a + 4) = *(const float4*)(xk + r0 + 4);
        *(float4*)(b)     = *(const float4*)(wk + c0);
        *(float4*)(b + 4) = *(const float4*)(wk + c0 + 4);
#pragma unroll
        for (int i = 0; i < 8; i++)
#pragma unroll
            for (int j = 0; j < 8; j++)
                acc[i][j] = fmaf(a[i], b[j], acc[i][j]);
    }

    // store h1
#pragma unroll
    for (int i = 0; i < 8; i++) {
        int gr = base + r0 + i;
        if (gr < N) {
            *(float4*)&g_h1[(size_t)gr * 128 + c0]     = make_float4(acc[i][0], acc[i][1], acc[i][2], acc[i][3]);
            *(float4*)&g_h1[(size_t)gr * 128 + c0 + 4] = make_float4(acc[i][4], acc[i][5], acc[i][6], acc[i][7]);
        }
    }

    // alpha partials: thread's 8 cols are inside one head (c0 multiple of 8, head = c0/32)
    float av[8], dv[8];
#pragma unroll
    for (int j = 0; j < 8; j++) { av[j] = asrc[c0 + j]; dv[j] = adst[c0 + j]; }
    __syncthreads();  // done reading xs/ws
#pragma unroll
    for (int i = 0; i < 8; i++) {
        float ps = 0.f, pd = 0.f;
#pragma unroll
        for (int j = 0; j < 8; j++) { ps = fmaf(acc[i][j], av[j], ps); pd = fmaf(acc[i][j], dv[j], pd); }
        rs[(r0 + i) * 16 + tx] = ps;
        rd[(r0 + i) * 16 + tx] = pd;
    }
    __syncthreads();
    if (tid < 128) {
        int gr = base + tid;
        if (gr < N) {
            float s[4], d[4];
#pragma unroll
            for (int h = 0; h < 4; h++) {
                float a0 = 0.f, a1 = 0.f;
#pragma unroll
                for (int q = 0; q < 4; q++) {
                    a0 += rs[tid * 16 + h * 4 + q];
                    a1 += rd[tid * 16 + h * 4 + q];
                }
                s[h] = a0; d[h] = a1;
            }
            g_as1[gr] = make_float4(s[0], s[1], s[2], s[3]);
            g_ad1[gr] = make_float4(d[0], d[1], d[2], d[3]);
        }
    }
}

// ---------------- layer1 fused softmax + aggregation: warp per dst ----------------
__global__ void agg1_kernel(int N) {
    int gw = (blockIdx.x * blockDim.x + threadIdx.x) >> 5;
    int lane = threadIdx.x & 31;
    if (gw >= N) return;
    int row = g_rowstart[gw], end = g_rowstart[gw + 1];
    float4 d4 = g_ad1[gw];

    // pass 1: online softmax stats per lane, then warp-combine
    float m0 = -1e30f, m1 = -1e30f, m2 = -1e30f, m3 = -1e30f;
    float s0 = 0.f, s1 = 0.f, s2 = 0.f, s3 = 0.f;
    for (int j = row + lane; j < end; j += 32) {
        int src = __ldg(&g_srcs[j]);
        float4 a = g_as1[src];
        float e0 = lrelu(a.x + d4.x), e1 = lrelu(a.y + d4.y);
        float e2 = lrelu(a.z + d4.z), e3 = lrelu(a.w + d4.w);
        float n0 = fmaxf(m0, e0); s0 = s0 * __expf(m0 - n0) + __expf(e0 - n0); m0 = n0;
        float n1 = fmaxf(m1, e1); s1 = s1 * __expf(m1 - n1) + __expf(e1 - n1); m1 = n1;
        float n2 = fmaxf(m2, e2); s2 = s2 * __expf(m2 - n2) + __expf(e2 - n2); m2 = n2;
        float n3 = fmaxf(m3, e3); s3 = s3 * __expf(m3 - n3) + __expf(e3 - n3); m3 = n3;
    }
    float M0 = wmaxf(m0), M1 = wmaxf(m1), M2 = wmaxf(m2), M3 = wmaxf(m3);
    float S0 = wsumf(s0 * __expf(m0 - M0));
    float S1 = wsumf(s1 * __expf(m1 - M1));
    float S2 = wsumf(s2 * __expf(m2 - M2));
    float S3 = wsumf(s3 * __expf(m3 - M3));
    float i0 = 1.f / (S0 + 1e-16f), i1 = 1.f / (S1 + 1e-16f);
    float i2 = 1.f / (S2 + 1e-16f), i3 = 1.f / (S3 + 1e-16f);

    // pass 2: weighted accumulation, coalesced 128B loads per edge
    float acc0 = 0.f, acc1 = 0.f, acc2 = 0.f, acc3 = 0.f;
#pragma unroll 2
    for (int j = row; j < end; j++) {
        int src = __ldg(&g_srcs[j]);          // same addr all lanes -> broadcast
        float4 a = g_as1[src];
        float w0 = __expf(lrelu(a.x + d4.x) - M0) * i0;
        float w1 = __expf(lrelu(a.y + d4.y) - M1) * i1;
        float w2 = __expf(lrelu(a.z + d4.z) - M2) * i2;
        float w3 = __expf(lrelu(a.w + d4.w) - M3) * i3;
        const float* hp = g_h1 + (size_t)src * 128;
        acc0 = fmaf(w0, hp[lane],      acc0);
        acc1 = fmaf(w1, hp[lane + 32], acc1);
        acc2 = fmaf(w2, hp[lane + 64], acc2);
        acc3 = fmaf(w3, hp[lane + 96], acc3);
    }
    float* op = g_out1 + (size_t)gw * 128;
    op[lane]      = acc0;
    op[lane + 32] = acc1;
    op[lane + 64] = acc2;
    op[lane + 96] = acc3;
}

// ---------------- layer2: h2 = elu(out1+b1) @ W2, plus attention scores ----------------
__global__ void layer2_kernel(const float* __restrict__ W2, const float* __restrict__ b1,
                              const float* __restrict__ asrc2, const float* __restrict__ adst2, int N) {
    __shared__ float w2s[128 * 8];
    __shared__ float b1s[128];
    __shared__ float s2s[8], d2s[8];
    int tid = threadIdx.x;
    for (int i = tid; i < 1024; i += 256) w2s[i] = W2[i];
    if (tid < 128) b1s[tid] = b1[tid];
    if (tid < 8) { s2s[tid] = asrc2[tid]; d2s[tid] = adst2[tid]; }
    __syncthreads();
    int n = blockIdx.x * 256 + tid;
    if (n >= N) return;
    float acc[8];
#pragma unroll
    for (int c = 0; c < 8; c++) acc[c] = 0.f;
    const float4* op = (const float4*)&g_out1[(size_t)n * 128];
#pragma unroll 8
    for (int k4 = 0; k4 < 32; k4++) {
        float4 v = op[k4];
        float vv[4] = {v.x, v.y, v.z, v.w};
#pragma unroll
        for (int j = 0; j < 4; j++) {
            int k = k4 * 4 + j;
            float tv = eluf(vv[j] + b1s[k]);
#pragma unroll
            for (int c = 0; c < 8; c++) acc[c] = fmaf(tv, w2s[k * 8 + c], acc[c]);
        }
    }
    ((float4*)&g_h2[n * 8])[0] = make_float4(acc[0], acc[1], acc[2], acc[3]);
    ((float4*)&g_h2[n * 8])[1] = make_float4(acc[4], acc[5], acc[6], acc[7]);
    float s = 0.f, d = 0.f;
#pragma unroll
    for (int c = 0; c < 8; c++) { s += acc[c] * s2s[c]; d += acc[c] * d2s[c]; }
    g_as2[n] = s;
    g_ad2[n] = d;
}

// ---------------- layer2 fused softmax + aggregation: warp per dst ----------------
__global__ void agg2_kernel(int N) {
    int gw = (blockIdx.x * blockDim.x + threadIdx.x) >> 5;
    int lane = threadIdx.x & 31;
    if (gw >= N) return;
    int row = g_rowstart[gw], end = g_rowstart[gw + 1];
    float dd = g_ad2[gw];

    float m = -1e30f, s = 0.f;
    for (int j = row + lane; j < end; j += 32) {
        int src = __ldg(&g_srcs[j]);
        float e = lrelu(g_as2[src] + dd);
        float nm = fmaxf(m, e);
        s = s * __expf(m - nm) + __expf(e - nm);
        m = nm;
    }
    float M = wmaxf(m);
    float S = wsumf(s * __expf(m - M));
    float inv = 1.f / (S + 1e-16f);

    float a0 = 0.f, a1 = 0.f, a2 = 0.f, a3 = 0.f, a4 = 0.f, a5 = 0.f, a6 = 0.f, a7 = 0.f;
    for (int j = row + lane; j < end; j += 32) {
        int src = __ldg(&g_srcs[j]);
        float w = __expf(lrelu(g_as2[src] + dd) - M) * inv;
        const float4* hp = (const float4*)(g_h2 + (size_t)src * 8);
        float4 v0 = hp[0], v1 = hp[1];
        a0 = fmaf(w, v0.x, a0); a1 = fmaf(w, v0.y, a1);
        a2 = fmaf(w, v0.z, a2); a3 = fmaf(w, v0.w, a3);
        a4 = fmaf(w, v1.x, a4); a5 = fmaf(w, v1.y, a5);
        a6 = fmaf(w, v1.z, a6); a7 = fmaf(w, v1.w, a7);
    }
    a0 = wsumf(a0); a1 = wsumf(a1); a2 = wsumf(a2); a3 = wsumf(a3);
    a4 = wsumf(a4); a5 = wsumf(a5); a6 = wsumf(a6); a7 = wsumf(a7);
    if (lane == 0) {
        float4* op = (float4*)(g_out2 + (size_t)gw * 8);
        op[0] = make_float4(a0, a1, a2, a3);
        op[1] = make_float4(a4, a5, a6, a7);
    }
}

// ---------------- final: sigmoid(elu(out2+b2) @ Wlin + blin) ----------------
__global__ void final_kernel(const float* __restrict__ b2, const float* __restrict__ Wlin,
                             const float* __restrict__ blin, float* __restrict__ out, int N) {
    int n = blockIdx.x * blockDim.x + threadIdx.x;
    if (n >= N) return;
    const float4* op = (const float4*)&g_out2[(size_t)n * 8];
    float4 v0 = op[0], v1 = op[1];
    float o[8] = {v0.x, v0.y, v0.z, v0.w, v1.x, v1.y, v1.z, v1.w};
    float y = blin[0];
#pragma unroll
    for (int j = 0; j < 8; j++) {
        float t = eluf(o[j] + b2[j]);
        y = fmaf(t, Wlin[j], y);
    }
    out[n] = 1.f / (1.f + __expf(-y));
}

// ---------------- launch ----------------
extern "C" void kernel_launch(void* const* d_in, const int* in_sizes, int n_in,
                              void* d_out, int out_size) {
    const float* x    = (const float*)d_in[0];
    const int*   ei   = (const int*)d_in[1];
    // d_in[2] edge_attr unused
    const float* W1   = (const float*)d_in[3];
    const float* as1  = (const float*)d_in[4];
    const float* ad1  = (const float*)d_in[5];
    const float* b1   = (const float*)d_in[6];
    const float* W2   = (const float*)d_in[7];
    const float* as2w = (const float*)d_in[8];
    const float* ad2w = (const float*)d_in[9];
    const float* b2   = (const float*)d_in[10];
    const float* Wlin = (const float*)d_in[11];
    const float* blin = (const float*)d_in[12];
    float* out = (float*)d_out;

    int N = in_sizes[0] / 128;
    int E = in_sizes[1] / 2;
    int Etot = E + N;
    int nch = (N + SCAN_CHUNK - 1) / SCAN_CHUNK;
    const int TB = 256;
    const int SMEM_GEMM = 2 * 128 * 132 * 4;

    cudaFuncSetAttribute(gemm1_kernel, cudaFuncAttributeMaxDynamicSharedMemorySize, SMEM_GEMM);

    // CSR build
    zero_deg_kernel<<<(N + TB - 1) / TB, TB>>>(N);
    count_kernel<<<(Etot + TB - 1) / TB, TB>>>(ei, E, Etot);
    scan1_kernel<<<nch, SCAN_CHUNK>>>(N);
    scan2_kernel<<<1, SCAN_CHUNK>>>(nch);
    scan3_kernel<<<nch, SCAN_CHUNK>>>(N, Etot);
    fill_kernel<<<(Etot + TB - 1) / TB, TB>>>(ei, E, Etot);
    // layer 1
    gemm1_kernel<<<(N + 127) / 128, 256, SMEM_GEMM>>>(x, W1, as1, ad1, N);
    agg1_kernel<<<(N * 32 + TB - 1) / TB, TB>>>(N);
    // layer 2
    layer2_kernel<<<(N + TB - 1) / TB, TB>>>(W2, b1, as2w, ad2w, N);
    agg2_kernel<<<(N * 32 + TB - 1) / TB, TB>>>(N);
    // output
    final_kernel<<<(N + TB - 1) / TB, TB>>>(b2, Wlin, blin, out, N);
}

// round 3
// speedup vs baseline: 2.7259x; 1.3228x over previous
#include <cuda_runtime.h>
#include <math.h>
#include <stdint.h>

#define NMAX 100000
#define EMAX 1600000
#define ETMAX (EMAX + NMAX)
#define SCAN_CHUNK 512

// ---------------- scratch (device globals; no allocation allowed) ----------------
__device__ float  g_h1[NMAX * 128];      // layer1 features (51.2 MB)
__device__ float  g_out1[NMAX * 128];    // layer1 aggregated (51.2 MB)
__device__ float4 g_as1[NMAX];           // alpha_src layer1 (4 heads)
__device__ float4 g_ad1[NMAX];           // alpha_dst layer1
__device__ float  g_h2[NMAX * 8];
__device__ float  g_as2[NMAX];
__device__ float  g_ad2[NMAX];
__device__ float  g_out2[NMAX * 8];
// CSR scratch
__device__ int    g_deg[NMAX];
__device__ int    g_rowstart[NMAX + 1];
__device__ int    g_fill[NMAX];
__device__ int    g_srcs[ETMAX];
__device__ int    g_csum[(NMAX + SCAN_CHUNK - 1) / SCAN_CHUNK];
__device__ int    g_coff[(NMAX + SCAN_CHUNK - 1) / SCAN_CHUNK];

// ---------------- helpers ----------------
__device__ __forceinline__ float lrelu(float v) { return v > 0.f ? v : 0.2f * v; }
__device__ __forceinline__ float eluf(float v)  { return v > 0.f ? v : (__expf(v) - 1.f); }
__device__ __forceinline__ float wmaxf(float v) {
#pragma unroll
    for (int o = 16; o; o >>= 1) v = fmaxf(v, __shfl_xor_sync(0xffffffffu, v, o));
    return v;
}
__device__ __forceinline__ float wsumf(float v) {
#pragma unroll
    for (int o = 16; o; o >>= 1) v += __shfl_xor_sync(0xffffffffu, v, o);
    return v;
}
__device__ __forceinline__ uint32_t f2tf32(float f) {
    uint32_t r; asm("cvt.rna.tf32.f32 %0, %1;" : "=r"(r) : "f"(f)); return r;
}
__device__ __forceinline__ void mma_tf32(float& d0, float& d1, float& d2, float& d3,
                                         uint32_t a0, uint32_t a1, uint32_t a2, uint32_t a3,
                                         uint32_t b0, uint32_t b1) {
    asm("mma.sync.aligned.m16n8k8.row.col.f32.tf32.tf32.f32 "
        "{%0,%1,%2,%3}, {%4,%5,%6,%7}, {%8,%9}, {%0,%1,%2,%3};"
        : "+f"(d0), "+f"(d1), "+f"(d2), "+f"(d3)
        : "r"(a0), "r"(a1), "r"(a2), "r"(a3), "r"(b0), "r"(b1));
}

// ---------------- CSR build ----------------
__global__ void zero_deg_kernel(int N) {
    int i = blockIdx.x * blockDim.x + threadIdx.x;
    if (i < N) g_deg[i] = 0;
}

__global__ void count_kernel(const int* __restrict__ ei, int E, int Etot) {
    int idx = blockIdx.x * blockDim.x + threadIdx.x;
    if (idx >= Etot) return;
    int dst = (idx < E) ? ei[E + idx] : (idx - E);
    atomicAdd(&g_deg[dst], 1);
}

__global__ void scan1_kernel(int N) {
    __shared__ int sh[SCAN_CHUNK];
    int t = threadIdx.x;
    int i = blockIdx.x * SCAN_CHUNK + t;
    sh[t] = (i < N) ? g_deg[i] : 0;
    __syncthreads();
#pragma unroll
    for (int s = SCAN_CHUNK / 2; s > 0; s >>= 1) {
        if (t < s) sh[t] += sh[t + s];
        __syncthreads();
    }
    if (t == 0) g_csum[blockIdx.x] = sh[0];
}

__global__ void scan2_kernel(int nch) {
    __shared__ int sh[SCAN_CHUNK];
    int t = threadIdx.x;
    int v = (t < nch) ? g_csum[t] : 0;
    sh[t] = v;
    __syncthreads();
#pragma unroll
    for (int off = 1; off < SCAN_CHUNK; off <<= 1) {
        int add = (t >= off) ? sh[t - off] : 0;
        __syncthreads();
        sh[t] += add;
        __syncthreads();
    }
    if (t < nch) g_coff[t] = sh[t] - v;
}

__global__ void scan3_kernel(int N, int Etot) {
    __shared__ int sh[SCAN_CHUNK];
    int t = threadIdx.x;
    int i = blockIdx.x * SCAN_CHUNK + t;
    int v = (i < N) ? g_deg[i] : 0;
    sh[t] = v;
    __syncthreads();
#pragma unroll
    for (int off = 1; off < SCAN_CHUNK; off <<= 1) {
        int add = (t >= off) ? sh[t - off] : 0;
        __syncthreads();
        sh[t] += add;
        __syncthreads();
    }
    if (i < N) {
        int excl = sh[t] - v + g_coff[blockIdx.x];
        g_rowstart[i] = excl;
        g_fill[i] = excl;
    }
    if (blockIdx.x == 0 && t == 0) g_rowstart[N] = Etot;
}

__global__ void fill_kernel(const int* __restrict__ ei, int E, int Etot) {
    int idx = blockIdx.x * blockDim.x + threadIdx.x;
    if (idx >= Etot) return;
    int src, dst;
    if (idx < E) { src = ei[idx]; dst = ei[E + idx]; } else { src = dst = idx - E; }
    int p = atomicAdd(&g_fill[dst], 1);
    g_srcs[p] = src;
}

// ---------------- layer1 GEMM (tf32 tensor cores) + fused alpha epilogue ----------------
// Block: 512 threads (16 warps), M-tile 256, N=K=128.
// smem: A tile [256][132] (tf32 bits), B tile W^T-access [128 k][136 n] (tf32 bits).
__global__ __launch_bounds__(512) void gemm1_kernel(
    const float* __restrict__ x, const float* __restrict__ W,
    const float* __restrict__ asrc, const float* __restrict__ adst, int N) {
    extern __shared__ float sm[];
    float* xs = sm;               // 256*132
    float* wk = sm + 256 * 132;   // 128*136
    int tid = threadIdx.x;
    int base = blockIdx.x * 256;

    // fill W tile: row k (128), cols n (128), direct copy with tf32 convert
    for (int i = tid; i < 4096; i += 512) {
        int k = i >> 5, c4 = i & 31;
        float4 v = ((const float4*)W)[i];
        float4 o;
        o.x = __uint_as_float(f2tf32(v.x));
        o.y = __uint_as_float(f2tf32(v.y));
        o.z = __uint_as_float(f2tf32(v.z));
        o.w = __uint_as_float(f2tf32(v.w));
        *(float4*)&wk[k * 136 + c4 * 4] = o;
    }
    // fill A tile: rows 256
    for (int i = tid; i < 8192; i += 512) {
        int r = i >> 5, c4 = i & 31;
        int gr = base + r;
        float4 v = make_float4(0.f, 0.f, 0.f, 0.f);
        if (gr < N) v = ((const float4*)x)[gr * 32 + c4];
        float4 o;
        o.x = __uint_as_float(f2tf32(v.x));
        o.y = __uint_as_float(f2tf32(v.y));
        o.z = __uint_as_float(f2tf32(v.z));
        o.w = __uint_as_float(f2tf32(v.w));
        *(float4*)&xs[r * 132 + c4 * 4] = o;
    }
    __syncthreads();

    int w = tid >> 5, lane = tid & 31;
    int tg = lane & 3, grp = lane >> 2;
    int r0 = w * 16;

    float acc[16][4];
#pragma unroll
    for (int j = 0; j < 16; j++)
#pragma unroll
        for (int q = 0; q < 4; q++) acc[j][q] = 0.f;

#pragma unroll 4
    for (int ks = 0; ks < 16; ks++) {
        int k0 = ks * 8;
        const float* ax = xs + (r0 + grp) * 132 + k0 + tg;
        uint32_t a0 = __float_as_uint(ax[0]);
        uint32_t a1 = __float_as_uint(ax[8 * 132]);
        uint32_t a2 = __float_as_uint(ax[4]);
        uint32_t a3 = __float_as_uint(ax[8 * 132 + 4]);
        const float* bx = wk + (k0 + tg) * 136 + grp;
#pragma unroll
        for (int j = 0; j < 16; j++) {
            uint32_t b0 = __float_as_uint(bx[8 * j]);
            uint32_t b1 = __float_as_uint(bx[4 * 136 + 8 * j]);
            mma_tf32(acc[j][0], acc[j][1], acc[j][2], acc[j][3], a0, a1, a2, a3, b0, b1);
        }
    }

    // ---- epilogue: store h1 + fused alpha dot products ----
    int gr0 = base + r0 + grp;
    int gr8 = gr0 + 8;
    float s_r0[4] = {0, 0, 0, 0}, s_r8[4] = {0, 0, 0, 0};
    float d_r0[4] = {0, 0, 0, 0}, d_r8[4] = {0, 0, 0, 0};
#pragma unroll
    for (int j = 0; j < 16; j++) {
        int c = 8 * j + 2 * tg;
        int h = j >> 2;
        float A0 = __ldg(&asrc[c]), A1 = __ldg(&asrc[c + 1]);
        float D0 = __ldg(&adst[c]), D1 = __ldg(&adst[c + 1]);
        s_r0[h] = fmaf(acc[j][0], A0, fmaf(acc[j][1], A1, s_r0[h]));
        s_r8[h] = fmaf(acc[j][2], A0, fmaf(acc[j][3], A1, s_r8[h]));
        d_r0[h] = fmaf(acc[j][0], D0, fmaf(acc[j][1], D1, d_r0[h]));
        d_r8[h] = fmaf(acc[j][2], D0, fmaf(acc[j][3], D1, d_r8[h]));
        if (gr0 < N) *(float2*)&g_h1[(size_t)gr0 * 128 + c] = make_float2(acc[j][0], acc[j][1]);
        if (gr8 < N) *(float2*)&g_h1[(size_t)gr8 * 128 + c] = make_float2(acc[j][2], acc[j][3]);
    }
    // quad reduce (over tg lanes)
#pragma unroll
    for (int h = 0; h < 4; h++) {
        s_r0[h] += __shfl_xor_sync(0xffffffffu, s_r0[h], 1);
        s_r0[h] += __shfl_xor_sync(0xffffffffu, s_r0[h], 2);
        s_r8[h] += __shfl_xor_sync(0xffffffffu, s_r8[h], 1);
        s_r8[h] += __shfl_xor_sync(0xffffffffu, s_r8[h], 2);
        d_r0[h] += __shfl_xor_sync(0xffffffffu, d_r0[h], 1);
        d_r0[h] += __shfl_xor_sync(0xffffffffu, d_r0[h], 2);
        d_r8[h] += __shfl_xor_sync(0xffffffffu, d_r8[h], 1);
        d_r8[h] += __shfl_xor_sync(0xffffffffu, d_r8[h], 2);
    }
    if (tg == 0) {
        if (gr0 < N) {
            g_as1[gr0] = make_float4(s_r0[0], s_r0[1], s_r0[2], s_r0[3]);
            g_ad1[gr0] = make_float4(d_r0[0], d_r0[1], d_r0[2], d_r0[3]);
        }
        if (gr8 < N) {
            g_as1[gr8] = make_float4(s_r8[0], s_r8[1], s_r8[2], s_r8[3]);
            g_ad1[gr8] = make_float4(d_r8[0], d_r8[1], d_r8[2], d_r8[3]);
        }
    }
}

// ---------------- layer1 fused softmax + aggregation: warp per dst ----------------
__global__ void agg1_kernel(int N) {
    int gw = (blockIdx.x * blockDim.x + threadIdx.x) >> 5;
    int lane = threadIdx.x & 31;
    if (gw >= N) return;
    int row = g_rowstart[gw], end = g_rowstart[gw + 1];
    float4 d4 = g_ad1[gw];

    // pass 1: online softmax stats
    float m0 = -1e30f, m1 = -1e30f, m2 = -1e30f, m3 = -1e30f;
    float s0 = 0.f, s1 = 0.f, s2 = 0.f, s3 = 0.f;
    for (int j = row + lane; j < end; j += 32) {
        int src = __ldg(&g_srcs[j]);
        float4 a = g_as1[src];
        float e0 = lrelu(a.x + d4.x), e1 = lrelu(a.y + d4.y);
        float e2 = lrelu(a.z + d4.z), e3 = lrelu(a.w + d4.w);
        float n0 = fmaxf(m0, e0); s0 = s0 * __expf(m0 - n0) + __expf(e0 - n0); m0 = n0;
        float n1 = fmaxf(m1, e1); s1 = s1 * __expf(m1 - n1) + __expf(e1 - n1); m1 = n1;
        float n2 = fmaxf(m2, e2); s2 = s2 * __expf(m2 - n2) + __expf(e2 - n2); m2 = n2;
        float n3 = fmaxf(m3, e3); s3 = s3 * __expf(m3 - n3) + __expf(e3 - n3); m3 = n3;
    }
    float M0 = wmaxf(m0), M1 = wmaxf(m1), M2 = wmaxf(m2), M3 = wmaxf(m3);
    float i0 = 1.f / (wsumf(s0 * __expf(m0 - M0)) + 1e-16f);
    float i1 = 1.f / (wsumf(s1 * __expf(m1 - M1)) + 1e-16f);
    float i2 = 1.f / (wsumf(s2 * __expf(m2 - M2)) + 1e-16f);
    float i3 = 1.f / (wsumf(s3 * __expf(m3 - M3)) + 1e-16f);

    // pass 2: lane-parallel weight precompute, shfl broadcast, float4 gather
    float4 acc = make_float4(0.f, 0.f, 0.f, 0.f);
    for (int cb = row; cb < end; cb += 32) {
        int rem = end - cb;
        int msrc = 0;
        float w0 = 0.f, w1 = 0.f, w2 = 0.f, w3 = 0.f;
        if (lane < rem) {
            msrc = __ldg(&g_srcs[cb + lane]);
            float4 a = g_as1[msrc];
            w0 = __expf(lrelu(a.x + d4.x) - M0) * i0;
            w1 = __expf(lrelu(a.y + d4.y) - M1) * i1;
            w2 = __expf(lrelu(a.z + d4.z) - M2) * i2;
            w3 = __expf(lrelu(a.w + d4.w) - M3) * i3;
        }
        int cnt = rem < 32 ? rem : 32;
#pragma unroll 4
        for (int e = 0; e < cnt; e++) {
            int   src = __shfl_sync(0xffffffffu, msrc, e);
            float e0  = __shfl_sync(0xffffffffu, w0, e);
            float e1  = __shfl_sync(0xffffffffu, w1, e);
            float e2  = __shfl_sync(0xffffffffu, w2, e);
            float e3  = __shfl_sync(0xffffffffu, w3, e);
            float wl = (lane & 8) ? e1 : e0;
            float wh = (lane & 8) ? e3 : e2;
            float ws = (lane & 16) ? wh : wl;
            float4 hv = *(const float4*)(g_h1 + (size_t)src * 128 + lane * 4);
            acc.x = fmaf(ws, hv.x, acc.x);
            acc.y = fmaf(ws, hv.y, acc.y);
            acc.z = fmaf(ws, hv.z, acc.z);
            acc.w = fmaf(ws, hv.w, acc.w);
        }
    }
    *(float4*)(g_out1 + (size_t)gw * 128 + lane * 4) = acc;
}

// ---------------- layer2: h2 = elu(out1+b1) @ W2, plus attention scores ----------------
__global__ void layer2_kernel(const float* __restrict__ W2, const float* __restrict__ b1,
                              const float* __restrict__ asrc2, const float* __restrict__ adst2, int N) {
    __shared__ float w2s[128 * 8];
    __shared__ float b1s[128];
    __shared__ float s2s[8], d2s[8];
    int tid = threadIdx.x;
    for (int i = tid; i < 1024; i += 256) w2s[i] = W2[i];
    if (tid < 128) b1s[tid] = b1[tid];
    if (tid < 8) { s2s[tid] = asrc2[tid]; d2s[tid] = adst2[tid]; }
    __syncthreads();
    int n = blockIdx.x * 256 + tid;
    if (n >= N) return;
    float acc[8];
#pragma unroll
    for (int c = 0; c < 8; c++) acc[c] = 0.f;
    const float4* op = (const float4*)&g_out1[(size_t)n * 128];
#pragma unroll 8
    for (int k4 = 0; k4 < 32; k4++) {
        float4 v = op[k4];
        float vv[4] = {v.x, v.y, v.z, v.w};
#pragma unroll
        for (int j = 0; j < 4; j++) {
            int k = k4 * 4 + j;
            float tv = eluf(vv[j] + b1s[k]);
#pragma unroll
            for (int c = 0; c < 8; c++) acc[c] = fmaf(tv, w2s[k * 8 + c], acc[c]);
        }
    }
    ((float4*)&g_h2[n * 8])[0] = make_float4(acc[0], acc[1], acc[2], acc[3]);
    ((float4*)&g_h2[n * 8])[1] = make_float4(acc[4], acc[5], acc[6], acc[7]);
    float s = 0.f, d = 0.f;
#pragma unroll
    for (int c = 0; c < 8; c++) { s += acc[c] * s2s[c]; d += acc[c] * d2s[c]; }
    g_as2[n] = s;
    g_ad2[n] = d;
}

// ---------------- layer2 fused softmax + aggregation ----------------
__global__ void agg2_kernel(int N) {
    int gw = (blockIdx.x * blockDim.x + threadIdx.x) >> 5;
    int lane = threadIdx.x & 31;
    if (gw >= N) return;
    int row = g_rowstart[gw], end = g_rowstart[gw + 1];
    float dd = g_ad2[gw];

    float m = -1e30f, s = 0.f;
    for (int j = row + lane; j < end; j += 32) {
        int src = __ldg(&g_srcs[j]);
        float e = lrelu(g_as2[src] + dd);
        float nm = fmaxf(m, e);
        s = s * __expf(m - nm) + __expf(e - nm);
        m = nm;
    }
    float M = wmaxf(m);
    float S = wsumf(s * __expf(m - M));
    float inv = 1.f / (S + 1e-16f);

    float a0 = 0.f, a1 = 0.f, a2 = 0.f, a3 = 0.f, a4 = 0.f, a5 = 0.f, a6 = 0.f, a7 = 0.f;
    for (int j = row + lane; j < end; j += 32) {
        int src = __ldg(&g_srcs[j]);
        float w = __expf(lrelu(g_as2[src] + dd) - M) * inv;
        const float4* hp = (const float4*)(g_h2 + (size_t)src * 8);
        float4 v0 = hp[0], v1 = hp[1];
        a0 = fmaf(w, v0.x, a0); a1 = fmaf(w, v0.y, a1);
        a2 = fmaf(w, v0.z, a2); a3 = fmaf(w, v0.w, a3);
        a4 = fmaf(w, v1.x, a4); a5 = fmaf(w, v1.y, a5);
        a6 = fmaf(w, v1.z, a6); a7 = fmaf(w, v1.w, a7);
    }
    a0 = wsumf(a0); a1 = wsumf(a1); a2 = wsumf(a2); a3 = wsumf(a3);
    a4 = wsumf(a4); a5 = wsumf(a5); a6 = wsumf(a6); a7 = wsumf(a7);
    if (lane == 0) {
        float4* op = (float4*)(g_out2 + (size_t)gw * 8);
        op[0] = make_float4(a0, a1, a2, a3);
        op[1] = make_float4(a4, a5, a6, a7);
    }
}

// ---------------- final: sigmoid(elu(out2+b2) @ Wlin + blin) ----------------
__global__ void final_kernel(const float* __restrict__ b2, const float* __restrict__ Wlin,
                             const float* __restrict__ blin, float* __restrict__ out, int N) {
    int n = blockIdx.x * blockDim.x + threadIdx.x;
    if (n >= N) return;
    const float4* op = (const float4*)&g_out2[(size_t)n * 8];
    float4 v0 = op[0], v1 = op[1];
    float o[8] = {v0.x, v0.y, v0.z, v0.w, v1.x, v1.y, v1.z, v1.w};
    float y = blin[0];
#pragma unroll
    for (int j = 0; j < 8; j++) {
        float t = eluf(o[j] + b2[j]);
        y = fmaf(t, Wlin[j], y);
    }
    out[n] = 1.f / (1.f + __expf(-y));
}

// ---------------- launch ----------------
extern "C" void kernel_launch(void* const* d_in, const int* in_sizes, int n_in,
                              void* d_out, int out_size) {
    const float* x    = (const float*)d_in[0];
    const int*   ei   = (const int*)d_in[1];
    // d_in[2] edge_attr unused
    const float* W1   = (const float*)d_in[3];
    const float* as1  = (const float*)d_in[4];
    const float* ad1  = (const float*)d_in[5];
    const float* b1   = (const float*)d_in[6];
    const float* W2   = (const float*)d_in[7];
    const float* as2w = (const float*)d_in[8];
    const float* ad2w = (const float*)d_in[9];
    const float* b2   = (const float*)d_in[10];
    const float* Wlin = (const float*)d_in[11];
    const float* blin = (const float*)d_in[12];
    float* out = (float*)d_out;

    int N = in_sizes[0] / 128;
    int E = in_sizes[1] / 2;
    int Etot = E + N;
    int nch = (N + SCAN_CHUNK - 1) / SCAN_CHUNK;
    const int TB = 256;
    const int SMEM_GEMM = (256 * 132 + 128 * 136) * 4;  // 204800 B

    cudaFuncSetAttribute(gemm1_kernel, cudaFuncAttributeMaxDynamicSharedMemorySize, SMEM_GEMM);

    // CSR build
    zero_deg_kernel<<<(N + TB - 1) / TB, TB>>>(N);
    count_kernel<<<(Etot + TB - 1) / TB, TB>>>(ei, E, Etot);
    scan1_kernel<<<nch, SCAN_CHUNK>>>(N);
    scan2_kernel<<<1, SCAN_CHUNK>>>(nch);
    scan3_kernel<<<nch, SCAN_CHUNK>>>(N, Etot);
    fill_kernel<<<(Etot + TB - 1) / TB, TB>>>(ei, E, Etot);
    // layer 1
    gemm1_kernel<<<(N + 255) / 256, 512, SMEM_GEMM>>>(x, W1, as1, ad1, N);
    agg1_kernel<<<(N * 32 + TB - 1) / TB, TB>>>(N);
    // layer 2
    layer2_kernel<<<(N + TB - 1) / TB, TB>>>(W2, b1, as2w, ad2w, N);
    agg2_kernel<<<(N * 32 + TB - 1) / TB, TB>>>(N);
    // output
    final_kernel<<<(N + TB - 1) / TB, TB>>>(b2, Wlin, blin, out, N);
}

// round 4
// speedup vs baseline: 3.0805x; 1.1301x over previous
#include <cuda_runtime.h>
#include <cuda_bf16.h>
#include <math.h>
#include <stdint.h>

#define NMAX 100000
#define EMAX 1600000
#define ETMAX (EMAX + NMAX)
#define SCAN_CHUNK 512

// ---------------- scratch (device globals; no allocation allowed) ----------------
__device__ __nv_bfloat16 g_h1b[NMAX * 128];  // layer1 features, bf16 (25.6 MB)
__device__ float  g_out1[NMAX * 128];        // layer1 aggregated (51.2 MB)
__device__ float4 g_as1[NMAX];               // alpha_src layer1 (4 heads)
__device__ float4 g_ad1[NMAX];               // alpha_dst layer1
__device__ float  g_h2[NMAX * 8];
__device__ float  g_as2[NMAX];
__device__ float  g_ad2[NMAX];
// CSR scratch
__device__ int    g_deg[NMAX];
__device__ int    g_rowstart[NMAX + 1];
__device__ int    g_fill[NMAX];
__device__ int    g_srcs[ETMAX];
__device__ int    g_csum[(NMAX + SCAN_CHUNK - 1) / SCAN_CHUNK];
__device__ int    g_coff[(NMAX + SCAN_CHUNK - 1) / SCAN_CHUNK];

// ---------------- helpers ----------------
__device__ __forceinline__ float lrelu(float v) { return v > 0.f ? v : 0.2f * v; }
__device__ __forceinline__ float eluf(float v)  { return v > 0.f ? v : (__expf(v) - 1.f); }
__device__ __forceinline__ float wmaxf(float v) {
#pragma unroll
    for (int o = 16; o; o >>= 1) v = fmaxf(v, __shfl_xor_sync(0xffffffffu, v, o));
    return v;
}
__device__ __forceinline__ float wsumf(float v) {
#pragma unroll
    for (int o = 16; o; o >>= 1) v += __shfl_xor_sync(0xffffffffu, v, o);
    return v;
}
__device__ __forceinline__ uint32_t f2tf32(float f) {
    uint32_t r; asm("cvt.rna.tf32.f32 %0, %1;" : "=r"(r) : "f"(f)); return r;
}
__device__ __forceinline__ void mma_tf32(float& d0, float& d1, float& d2, float& d3,
                                         uint32_t a0, uint32_t a1, uint32_t a2, uint32_t a3,
                                         uint32_t b0, uint32_t b1) {
    asm("mma.sync.aligned.m16n8k8.row.col.f32.tf32.tf32.f32 "
        "{%0,%1,%2,%3}, {%4,%5,%6,%7}, {%8,%9}, {%0,%1,%2,%3};"
        : "+f"(d0), "+f"(d1), "+f"(d2), "+f"(d3)
        : "r"(a0), "r"(a1), "r"(a2), "r"(a3), "r"(b0), "r"(b1));
}

// ---------------- CSR build ----------------
__global__ void zero_deg_kernel(int N) {
    int i = blockIdx.x * blockDim.x + threadIdx.x;
    if (i < N) g_deg[i] = 0;
}

__global__ void count_kernel(const int* __restrict__ ei, int E, int Etot) {
    int idx = blockIdx.x * blockDim.x + threadIdx.x;
    if (idx >= Etot) return;
    int dst = (idx < E) ? ei[E + idx] : (idx - E);
    atomicAdd(&g_deg[dst], 1);
}

__global__ void scan1_kernel(int N) {
    __shared__ int sh[SCAN_CHUNK];
    int t = threadIdx.x;
    int i = blockIdx.x * SCAN_CHUNK + t;
    sh[t] = (i < N) ? g_deg[i] : 0;
    __syncthreads();
#pragma unroll
    for (int s = SCAN_CHUNK / 2; s > 0; s >>= 1) {
        if (t < s) sh[t] += sh[t + s];
        __syncthreads();
    }
    if (t == 0) g_csum[blockIdx.x] = sh[0];
}

__global__ void scan2_kernel(int nch) {
    __shared__ int sh[SCAN_CHUNK];
    int t = threadIdx.x;
    int v = (t < nch) ? g_csum[t] : 0;
    sh[t] = v;
    __syncthreads();
#pragma unroll
    for (int off = 1; off < SCAN_CHUNK; off <<= 1) {
        int add = (t >= off) ? sh[t - off] : 0;
        __syncthreads();
        sh[t] += add;
        __syncthreads();
    }
    if (t < nch) g_coff[t] = sh[t] - v;
}

__global__ void scan3_kernel(int N, int Etot) {
    __shared__ int sh[SCAN_CHUNK];
    int t = threadIdx.x;
    int i = blockIdx.x * SCAN_CHUNK + t;
    int v = (i < N) ? g_deg[i] : 0;
    sh[t] = v;
    __syncthreads();
#pragma unroll
    for (int off = 1; off < SCAN_CHUNK; off <<= 1) {
        int add = (t >= off) ? sh[t - off] : 0;
        __syncthreads();
        sh[t] += add;
        __syncthreads();
    }
    if (i < N) {
        int excl = sh[t] - v + g_coff[blockIdx.x];
        g_rowstart[i] = excl;
        g_fill[i] = excl;
    }
    if (blockIdx.x == 0 && t == 0) g_rowstart[N] = Etot;
}

__global__ void fill_kernel(const int* __restrict__ ei, int E, int Etot) {
    int idx = blockIdx.x * blockDim.x + threadIdx.x;
    if (idx >= Etot) return;
    int src, dst;
    if (idx < E) { src = ei[idx]; dst = ei[E + idx]; } else { src = dst = idx - E; }
    int p = atomicAdd(&g_fill[dst], 1);
    g_srcs[p] = src;
}

// ---------------- layer1 GEMM (tf32 tensor cores) + fused alpha epilogue ----------------
__global__ __launch_bounds__(512) void gemm1_kernel(
    const float* __restrict__ x, const float* __restrict__ W,
    const float* __restrict__ asrc, const float* __restrict__ adst, int N) {
    extern __shared__ float sm[];
    float* xs = sm;               // 256*132
    float* wk = sm + 256 * 132;   // 128*136
    int tid = threadIdx.x;
    int base = blockIdx.x * 256;

    for (int i = tid; i < 4096; i += 512) {
        int k = i >> 5, c4 = i & 31;
        float4 v = ((const float4*)W)[i];
        float4 o;
        o.x = __uint_as_float(f2tf32(v.x));
        o.y = __uint_as_float(f2tf32(v.y));
        o.z = __uint_as_float(f2tf32(v.z));
        o.w = __uint_as_float(f2tf32(v.w));
        *(float4*)&wk[k * 136 + c4 * 4] = o;
    }
    for (int i = tid; i < 8192; i += 512) {
        int r = i >> 5, c4 = i & 31;
        int gr = base + r;
        float4 v = make_float4(0.f, 0.f, 0.f, 0.f);
        if (gr < N) v = ((const float4*)x)[gr * 32 + c4];
        float4 o;
        o.x = __uint_as_float(f2tf32(v.x));
        o.y = __uint_as_float(f2tf32(v.y));
        o.z = __uint_as_float(f2tf32(v.z));
        o.w = __uint_as_float(f2tf32(v.w));
        *(float4*)&xs[r * 132 + c4 * 4] = o;
    }
    __syncthreads();

    int w = tid >> 5, lane = tid & 31;
    int tg = lane & 3, grp = lane >> 2;
    int r0 = w * 16;

    float acc[16][4];
#pragma unroll
    for (int j = 0; j < 16; j++)
#pragma unroll
        for (int q = 0; q < 4; q++) acc[j][q] = 0.f;

#pragma unroll 4
    for (int ks = 0; ks < 16; ks++) {
        int k0 = ks * 8;
        const float* ax = xs + (r0 + grp) * 132 + k0 + tg;
        uint32_t a0 = __float_as_uint(ax[0]);
        uint32_t a1 = __float_as_uint(ax[8 * 132]);
        uint32_t a2 = __float_as_uint(ax[4]);
        uint32_t a3 = __float_as_uint(ax[8 * 132 + 4]);
        const float* bx = wk + (k0 + tg) * 136 + grp;
#pragma unroll
        for (int j = 0; j < 16; j++) {
            uint32_t b0 = __float_as_uint(bx[8 * j]);
            uint32_t b1 = __float_as_uint(bx[4 * 136 + 8 * j]);
            mma_tf32(acc[j][0], acc[j][1], acc[j][2], acc[j][3], a0, a1, a2, a3, b0, b1);
        }
    }

    // ---- epilogue: store h1 (bf16) + fused alpha dot products ----
    int gr0 = base + r0 + grp;
    int gr8 = gr0 + 8;
    float s_r0[4] = {0, 0, 0, 0}, s_r8[4] = {0, 0, 0, 0};
    float d_r0[4] = {0, 0, 0, 0}, d_r8[4] = {0, 0, 0, 0};
#pragma unroll
    for (int j = 0; j < 16; j++) {
        int c = 8 * j + 2 * tg;
        int h = j >> 2;
        float A0 = __ldg(&asrc[c]), A1 = __ldg(&asrc[c + 1]);
        float D0 = __ldg(&adst[c]), D1 = __ldg(&adst[c + 1]);
        s_r0[h] = fmaf(acc[j][0], A0, fmaf(acc[j][1], A1, s_r0[h]));
        s_r8[h] = fmaf(acc[j][2], A0, fmaf(acc[j][3], A1, s_r8[h]));
        d_r0[h] = fmaf(acc[j][0], D0, fmaf(acc[j][1], D1, d_r0[h]));
        d_r8[h] = fmaf(acc[j][2], D0, fmaf(acc[j][3], D1, d_r8[h]));
        if (gr0 < N)
            *(__nv_bfloat162*)&g_h1b[(size_t)gr0 * 128 + c] =
                __float22bfloat162_rn(make_float2(acc[j][0], acc[j][1]));
        if (gr8 < N)
            *(__nv_bfloat162*)&g_h1b[(size_t)gr8 * 128 + c] =
                __float22bfloat162_rn(make_float2(acc[j][2], acc[j][3]));
    }
#pragma unroll
    for (int h = 0; h < 4; h++) {
        s_r0[h] += __shfl_xor_sync(0xffffffffu, s_r0[h], 1);
        s_r0[h] += __shfl_xor_sync(0xffffffffu, s_r0[h], 2);
        s_r8[h] += __shfl_xor_sync(0xffffffffu, s_r8[h], 1);
        s_r8[h] += __shfl_xor_sync(0xffffffffu, s_r8[h], 2);
        d_r0[h] += __shfl_xor_sync(0xffffffffu, d_r0[h], 1);
        d_r0[h] += __shfl_xor_sync(0xffffffffu, d_r0[h], 2);
        d_r8[h] += __shfl_xor_sync(0xffffffffu, d_r8[h], 1);
        d_r8[h] += __shfl_xor_sync(0xffffffffu, d_r8[h], 2);
    }
    if (tg == 0) {
        if (gr0 < N) {
            g_as1[gr0] = make_float4(s_r0[0], s_r0[1], s_r0[2], s_r0[3]);
            g_ad1[gr0] = make_float4(d_r0[0], d_r0[1], d_r0[2], d_r0[3]);
        }
        if (gr8 < N) {
            g_as1[gr8] = make_float4(s_r8[0], s_r8[1], s_r8[2], s_r8[3]);
            g_ad1[gr8] = make_float4(d_r8[0], d_r8[1], d_r8[2], d_r8[3]);
        }
    }
}

// ---------------- layer1 fused softmax + aggregation: warp per dst ----------------
__global__ void agg1_kernel(int N) {
    int gw = (blockIdx.x * blockDim.x + threadIdx.x) >> 5;
    int lane = threadIdx.x & 31;
    if (gw >= N) return;
    int row = g_rowstart[gw], end = g_rowstart[gw + 1];
    int deg = end - row;
    float4 d4 = g_ad1[gw];
    float4 acc = make_float4(0.f, 0.f, 0.f, 0.f);

    if (deg <= 32) {
        // fast path: one gather, weights live in registers
        int msrc = 0;
        float e0 = -1e30f, e1 = -1e30f, e2 = -1e30f, e3 = -1e30f;
        if (lane < deg) {
            msrc = __ldg(&g_srcs[row + lane]);
            float4 a = g_as1[msrc];
            e0 = lrelu(a.x + d4.x); e1 = lrelu(a.y + d4.y);
            e2 = lrelu(a.z + d4.z); e3 = lrelu(a.w + d4.w);
        }
        float M0 = wmaxf(e0), M1 = wmaxf(e1), M2 = wmaxf(e2), M3 = wmaxf(e3);
        float t0 = (lane < deg) ? __expf(e0 - M0) : 0.f;
        float t1 = (lane < deg) ? __expf(e1 - M1) : 0.f;
        float t2 = (lane < deg) ? __expf(e2 - M2) : 0.f;
        float t3 = (lane < deg) ? __expf(e3 - M3) : 0.f;
        float w0 = t0 / (wsumf(t0) + 1e-16f);
        float w1 = t1 / (wsumf(t1) + 1e-16f);
        float w2 = t2 / (wsumf(t2) + 1e-16f);
        float w3 = t3 / (wsumf(t3) + 1e-16f);
#pragma unroll 4
        for (int e = 0; e < deg; e++) {
            int   src = __shfl_sync(0xffffffffu, msrc, e);
            float b0  = __shfl_sync(0xffffffffu, w0, e);
            float b1  = __shfl_sync(0xffffffffu, w1, e);
            float b2  = __shfl_sync(0xffffffffu, w2, e);
            float b3  = __shfl_sync(0xffffffffu, w3, e);
            float wl = (lane & 8) ? b1 : b0;
            float wh = (lane & 8) ? b3 : b2;
            float ws = (lane & 16) ? wh : wl;
            uint2 hv = *(const uint2*)(g_h1b + (size_t)src * 128 + lane * 4);
            float2 f0 = __bfloat1622float2(*(__nv_bfloat162*)&hv.x);
            float2 f1 = __bfloat1622float2(*(__nv_bfloat162*)&hv.y);
            acc.x = fmaf(ws, f0.x, acc.x);
            acc.y = fmaf(ws, f0.y, acc.y);
            acc.z = fmaf(ws, f1.x, acc.z);
            acc.w = fmaf(ws, f1.y, acc.w);
        }
    } else {
        // slow path (rare): 2-pass online softmax
        float m0 = -1e30f, m1 = -1e30f, m2 = -1e30f, m3 = -1e30f;
        float s0 = 0.f, s1 = 0.f, s2 = 0.f, s3 = 0.f;
        for (int j = row + lane; j < end; j += 32) {
            int src = __ldg(&g_srcs[j]);
            float4 a = g_as1[src];
            float e0 = lrelu(a.x + d4.x), e1 = lrelu(a.y + d4.y);
            float e2 = lrelu(a.z + d4.z), e3 = lrelu(a.w + d4.w);
            float n0 = fmaxf(m0, e0); s0 = s0 * __expf(m0 - n0) + __expf(e0 - n0); m0 = n0;
            float n1 = fmaxf(m1, e1); s1 = s1 * __expf(m1 - n1) + __expf(e1 - n1); m1 = n1;
            float n2 = fmaxf(m2, e2); s2 = s2 * __expf(m2 - n2) + __expf(e2 - n2); m2 = n2;
            float n3 = fmaxf(m3, e3); s3 = s3 * __expf(m3 - n3) + __expf(e3 - n3); m3 = n3;
        }
        float M0 = wmaxf(m0), M1 = wmaxf(m1), M2 = wmaxf(m2), M3 = wmaxf(m3);
        float i0 = 1.f / (wsumf(s0 * __expf(m0 - M0)) + 1e-16f);
        float i1 = 1.f / (wsumf(s1 * __expf(m1 - M1)) + 1e-16f);
        float i2 = 1.f / (wsumf(s2 * __expf(m2 - M2)) + 1e-16f);
        float i3 = 1.f / (wsumf(s3 * __expf(m3 - M3)) + 1e-16f);
        for (int cb = row; cb < end; cb += 32) {
            int rem = end - cb;
            int msrc = 0;
            float w0 = 0.f, w1 = 0.f, w2 = 0.f, w3 = 0.f;
            if (lane < rem) {
                msrc = __ldg(&g_srcs[cb + lane]);
                float4 a = g_as1[msrc];
                w0 = __expf(lrelu(a.x + d4.x) - M0) * i0;
                w1 = __expf(lrelu(a.y + d4.y) - M1) * i1;
                w2 = __expf(lrelu(a.z + d4.z) - M2) * i2;
                w3 = __expf(lrelu(a.w + d4.w) - M3) * i3;
            }
            int cnt = rem < 32 ? rem : 32;
            for (int e = 0; e < cnt; e++) {
                int   src = __shfl_sync(0xffffffffu, msrc, e);
                float b0  = __shfl_sync(0xffffffffu, w0, e);
                float b1  = __shfl_sync(0xffffffffu, w1, e);
                float b2  = __shfl_sync(0xffffffffu, w2, e);
                float b3  = __shfl_sync(0xffffffffu, w3, e);
                float wl = (lane & 8) ? b1 : b0;
                float wh = (lane & 8) ? b3 : b2;
                float ws = (lane & 16) ? wh : wl;
                uint2 hv = *(const uint2*)(g_h1b + (size_t)src * 128 + lane * 4);
                float2 f0 = __bfloat1622float2(*(__nv_bfloat162*)&hv.x);
                float2 f1 = __bfloat1622float2(*(__nv_bfloat162*)&hv.y);
                acc.x = fmaf(ws, f0.x, acc.x);
                acc.y = fmaf(ws, f0.y, acc.y);
                acc.z = fmaf(ws, f1.x, acc.z);
                acc.w = fmaf(ws, f1.y, acc.w);
            }
        }
    }
    *(float4*)(g_out1 + (size_t)gw * 128 + lane * 4) = acc;
}

// ---------------- layer2: h2 = elu(out1+b1) @ W2, plus attention scores ----------------
__global__ void layer2_kernel(const float* __restrict__ W2, const float* __restrict__ b1,
                              const float* __restrict__ asrc2, const float* __restrict__ adst2, int N) {
    __shared__ float w2s[128 * 8];
    __shared__ float b1s[128];
    __shared__ float s2s[8], d2s[8];
    int tid = threadIdx.x;
    for (int i = tid; i < 1024; i += 256) w2s[i] = W2[i];
    if (tid < 128) b1s[tid] = b1[tid];
    if (tid < 8) { s2s[tid] = asrc2[tid]; d2s[tid] = adst2[tid]; }
    __syncthreads();
    int n = blockIdx.x * 256 + tid;
    if (n >= N) return;
    float acc[8];
#pragma unroll
    for (int c = 0; c < 8; c++) acc[c] = 0.f;
    const float4* op = (const float4*)&g_out1[(size_t)n * 128];
#pragma unroll 8
    for (int k4 = 0; k4 < 32; k4++) {
        float4 v = op[k4];
        float vv[4] = {v.x, v.y, v.z, v.w};
#pragma unroll
        for (int j = 0; j < 4; j++) {
            int k = k4 * 4 + j;
            float tv = eluf(vv[j] + b1s[k]);
#pragma unroll
            for (int c = 0; c < 8; c++) acc[c] = fmaf(tv, w2s[k * 8 + c], acc[c]);
        }
    }
    ((float4*)&g_h2[n * 8])[0] = make_float4(acc[0], acc[1], acc[2], acc[3]);
    ((float4*)&g_h2[n * 8])[1] = make_float4(acc[4], acc[5], acc[6], acc[7]);
    float s = 0.f, d = 0.f;
#pragma unroll
    for (int c = 0; c < 8; c++) { s += acc[c] * s2s[c]; d += acc[c] * d2s[c]; }
    g_as2[n] = s;
    g_ad2[n] = d;
}

// ---------------- layer2 softmax + aggregation + final output (fused) ----------------
__global__ void agg2_final_kernel(const float* __restrict__ b2, const float* __restrict__ Wlin,
                                  const float* __restrict__ blin, float* __restrict__ out, int N) {
    int gw = (blockIdx.x * blockDim.x + threadIdx.x) >> 5;
    int lane = threadIdx.x & 31;
    if (gw >= N) return;
    int row = g_rowstart[gw], end = g_rowstart[gw + 1];
    float dd = g_ad2[gw];

    float m = -1e30f, s = 0.f;
    for (int j = row + lane; j < end; j += 32) {
        int src = __ldg(&g_srcs[j]);
        float e = lrelu(g_as2[src] + dd);
        float nm = fmaxf(m, e);
        s = s * __expf(m - nm) + __expf(e - nm);
        m = nm;
    }
    float M = wmaxf(m);
    float S = wsumf(s * __expf(m - M));
    float inv = 1.f / (S + 1e-16f);

    float a0 = 0.f, a1 = 0.f, a2 = 0.f, a3 = 0.f, a4 = 0.f, a5 = 0.f, a6 = 0.f, a7 = 0.f;
    for (int j = row + lane; j < end; j += 32) {
        int src = __ldg(&g_srcs[j]);
        float w = __expf(lrelu(g_as2[src] + dd) - M) * inv;
        const float4* hp = (const float4*)(g_h2 + (size_t)src * 8);
        float4 v0 = hp[0], v1 = hp[1];
        a0 = fmaf(w, v0.x, a0); a1 = fmaf(w, v0.y, a1);
        a2 = fmaf(w, v0.z, a2); a3 = fmaf(w, v0.w, a3);
        a4 = fmaf(w, v1.x, a4); a5 = fmaf(w, v1.y, a5);
        a6 = fmaf(w, v1.z, a6); a7 = fmaf(w, v1.w, a7);
    }
    a0 = wsumf(a0); a1 = wsumf(a1); a2 = wsumf(a2); a3 = wsumf(a3);
    a4 = wsumf(a4); a5 = wsumf(a5); a6 = wsumf(a6); a7 = wsumf(a7);
    if (lane == 0) {
        float o[8] = {a0, a1, a2, a3, a4, a5, a6, a7};
        float y = __ldg(&blin[0]);
#pragma unroll
        for (int j = 0; j < 8; j++) {
            float t = eluf(o[j] + __ldg(&b2[j]));
            y = fmaf(t, __ldg(&Wlin[j]), y);
        }
        out[gw] = 1.f / (1.f + __expf(-y));
    }
}

// ---------------- launch ----------------
extern "C" void kernel_launch(void* const* d_in, const int* in_sizes, int n_in,
                              void* d_out, int out_size) {
    const float* x    = (const float*)d_in[0];
    const int*   ei   = (const int*)d_in[1];
    // d_in[2] edge_attr unused
    const float* W1   = (const float*)d_in[3];
    const float* as1  = (const float*)d_in[4];
    const float* ad1  = (const float*)d_in[5];
    const float* b1   = (const float*)d_in[6];
    const float* W2   = (const float*)d_in[7];
    const float* as2w = (const float*)d_in[8];
    const float* ad2w = (const float*)d_in[9];
    const float* b2   = (const float*)d_in[10];
    const float* Wlin = (const float*)d_in[11];
    const float* blin = (const float*)d_in[12];
    float* out = (float*)d_out;

    int N = in_sizes[0] / 128;
    int E = in_sizes[1] / 2;
    int Etot = E + N;
    int nch = (N + SCAN_CHUNK - 1) / SCAN_CHUNK;
    const int TB = 256;
    const int SMEM_GEMM = (256 * 132 + 128 * 136) * 4;  // 204800 B

    cudaFuncSetAttribute(gemm1_kernel, cudaFuncAttributeMaxDynamicSharedMemorySize, SMEM_GEMM);

    // Fork: CSR build (ei only) runs concurrently with gemm1 (x/W1 only).
    cudaStream_t s2;
    cudaStreamCreate(&s2);
    cudaEvent_t evFork, evJoin;
    cudaEventCreateWithFlags(&evFork, cudaEventDisableTiming);
    cudaEventCreateWithFlags(&evJoin, cudaEventDisableTiming);

    cudaEventRecord(evFork, 0);
    cudaStreamWaitEvent(s2, evFork, 0);

    // CSR build on s2
    zero_deg_kernel<<<(N + TB - 1) / TB, TB, 0, s2>>>(N);
    count_kernel<<<(Etot + TB - 1) / TB, TB, 0, s2>>>(ei, E, Etot);
    scan1_kernel<<<nch, SCAN_CHUNK, 0, s2>>>(N);
    scan2_kernel<<<1, SCAN_CHUNK, 0, s2>>>(nch);
    scan3_kernel<<<nch, SCAN_CHUNK, 0, s2>>>(N, Etot);
    fill_kernel<<<(Etot + TB - 1) / TB, TB, 0, s2>>>(ei, E, Etot);
    cudaEventRecord(evJoin, s2);

    // gemm1 on main stream, concurrent with CSR chain
    gemm1_kernel<<<(N + 255) / 256, 512, SMEM_GEMM>>>(x, W1, as1, ad1, N);

    // join, then dependent chain
    cudaStreamWaitEvent(0, evJoin, 0);
    agg1_kernel<<<(N * 32 + TB - 1) / TB, TB>>>(N);
    layer2_kernel<<<(N + TB - 1) / TB, TB>>>(W2, b1, as2w, ad2w, N);
    agg2_final_kernel<<<(N * 32 + TB - 1) / TB, TB>>>(b2, Wlin, blin, out, N);

    cudaEventDestroy(evFork);
    cudaEventDestroy(evJoin);
    cudaStreamDestroy(s2);
}